// round 8
// baseline (speedup 1.0000x reference)
#include <cuda_runtime.h>
#include <cuda_fp16.h>

// 3-layer GCN, bucket-grouped aggregation, fp16 message payloads.
//   ht = (hW)*isq per node (fp16);  acc[d] = ht[d] + sum_{s->d} ht[s] (fp32);
//   next layer input = relu(isq*acc + b). One edge pass builds per-dst buckets.
// edge_index arrives as int32 (JAX x64-disabled demotes int64).

#define GN 100000
#define GE 3200000
#define GK 512
#define GC 16
#define CAP 128      // bucket slots per node; P(deg>128) ~ 1e-60
#define WPITCH 18    // W1 smem pitch (floats); 8B-aligned accesses only

// ---------------- scratch (static device globals) ----------------------------
__device__ __align__(256) float  g_isq[GN];
__device__ __align__(256) __half g_ht1[GN * GC];
__device__ __align__(256) __half g_ht2[GN * GC];
__device__ __align__(256) float  g_ht3[GN];
__device__ __align__(256) int    g_cnt[GN];
__device__ __align__(256) int    g_bucket[(size_t)GN * CAP];  // 51.2 MB

// ---------------- helpers -----------------------------------------------------
__device__ __forceinline__ unsigned long long ffma2(unsigned long long a,
                                                    unsigned long long b,
                                                    unsigned long long c) {
    unsigned long long d;
    asm("fma.rn.f32x2 %0, %1, %2, %3;" : "=l"(d) : "l"(a), "l"(b), "l"(c));
    return d;
}
__device__ __forceinline__ unsigned long long addf2(unsigned long long a,
                                                    unsigned long long b) {
    unsigned long long d;
    asm("add.rn.f32x2 %0, %1, %2;" : "=l"(d) : "l"(a), "l"(b));
    return d;
}
__device__ __forceinline__ unsigned long long pack2(float a) {
    unsigned long long r;
    unsigned u = __float_as_uint(a);
    asm("mov.b64 %0, {%1, %1};" : "=l"(r) : "r"(u));
    return r;
}

// gather 4 fp16 channels (q-th quad) of node s as float4
__device__ __forceinline__ float4 gat4(const uint2* __restrict__ htp, int s, int q) {
    uint2 u = __ldg(htp + (size_t)s * 4 + q);
    __half2 h0 = *(__half2*)&u.x;
    __half2 h1 = *(__half2*)&u.y;
    float2 a = __half22float2(h0), b = __half22float2(h1);
    return make_float4(a.x, a.y, b.x, b.y);
}

// ---------------- prep -------------------------------------------------------
__global__ void k_zero(int n) {
    int i = blockIdx.x * blockDim.x + threadIdx.x;
    if (i < n) g_cnt[i] = 0;
}

// single edge pass: count + bucket fill
__global__ void k_build(const int* __restrict__ ei, int e, int n) {
    int i = blockIdx.x * blockDim.x + threadIdx.x;
    if (i >= e) return;
    int s = ei[i];
    int d = ei[e + i];
    if ((unsigned)s >= (unsigned)n || (unsigned)d >= (unsigned)n) return;
    int pos = atomicAdd(&g_cnt[d], 1);
    if (pos < CAP) g_bucket[(size_t)d * CAP + pos] = s;
}

__global__ void k_isqrt(int n) {
    int i = blockIdx.x * blockDim.x + threadIdx.x;
    if (i < n) g_isq[i] = rsqrtf((float)g_cnt[i] + 1.0f);
}

// ---------------- GEMM1: ht1 = fp16((x @ W1) * isq) --------------------------
// 128 thr = 4 warps/block, block = 128 rows. Lane: g = k-quarter (lane&3),
// slot = lane>>2; lane owns 4 rows (slot + 8*r) x 16 ch in packed f32x2 accs.
// W LDS.64 broadcasts across the 8 slots and amortizes over 4 rows.
// Register diet: 32-bit clamped row offsets, no cached W array, occ cap 5.
__global__ void __launch_bounds__(128, 5) k_gemm1(const float* __restrict__ x,
                                                  const float* __restrict__ W1,
                                                  int n) {
    __shared__ float sW[GK * WPITCH];  // 36 KB
    int t = threadIdx.x;
    // stage W1 [512][16] -> sW[k*18 + c], float2 granularity (8B-aligned)
#pragma unroll
    for (int j = 0; j < 32; j++) {
        int idx = t + 128 * j;        // 0..4095 float2s
        int k = idx >> 3, pr = idx & 7;
        float2 w = *(const float2*)(W1 + (size_t)k * GC + 2 * pr);
        *(float2*)(sW + k * WPITCH + 2 * pr) = w;
    }
    __syncthreads();

    int lane = t & 31;
    int wid = t >> 5;
    int g = lane & 3;
    int slot = lane >> 2;
    int base = blockIdx.x * 128 + wid * 32 + slot;   // rows: base + 8*r

    // clamped float4-row offsets (OOB rows read row n-1; stores guarded later)
    unsigned roff[4];
#pragma unroll
    for (int r = 0; r < 4; r++) {
        int row = base + 8 * r;
        if (row >= n) row = n - 1;
        roff[r] = (unsigned)row * (GK / 4);
    }
    const float4* __restrict__ xb = (const float4*)x;

    unsigned long long acc[4][8];
#pragma unroll
    for (int r = 0; r < 4; r++)
#pragma unroll
        for (int p = 0; p < 8; p++) acc[r][p] = 0ull;

#pragma unroll 2
    for (int c = 0; c < 32; c++) {
        float4 xv[4];
#pragma unroll
        for (int r = 0; r < 4; r++)
            xv[r] = __ldg(xb + roff[r] + 4 * c + g);
        int kbase = 16 * c + 4 * g;
#pragma unroll
        for (int kk = 0; kk < 4; kk++) {
            const unsigned long long* wr =
                (const unsigned long long*)(sW + (kbase + kk) * WPITCH);
#pragma unroll
            for (int p = 0; p < 8; p++) {
                unsigned long long w2 = wr[p];
#pragma unroll
                for (int r = 0; r < 4; r++) {
                    const float* xf = (const float*)&xv[r];
                    acc[r][p] = ffma2(pack2(xf[kk]), w2, acc[r][p]);
                }
            }
        }
    }

    // butterfly over the 4 k-quarters, packed adds
#pragma unroll
    for (int off = 1; off <= 2; off <<= 1)
#pragma unroll
        for (int r = 0; r < 4; r++)
#pragma unroll
            for (int p = 0; p < 8; p++)
                acc[r][p] = addf2(acc[r][p],
                                  __shfl_xor_sync(0xffffffffu, acc[r][p], off));

    // lane g writes channel quad 4g..4g+3 (pairs 2g, 2g+1) for its 4 rows
#pragma unroll
    for (int r = 0; r < 4; r++) {
        int row = base + 8 * r;
        if (row < n) {
            float s = g_isq[row];
            unsigned lo0, hi0, lo1, hi1;
            asm("mov.b64 {%0,%1}, %2;" : "=r"(lo0), "=r"(hi0) : "l"(acc[r][2 * g]));
            asm("mov.b64 {%0,%1}, %2;" : "=r"(lo1), "=r"(hi1) : "l"(acc[r][2 * g + 1]));
            __half2 h0 = __floats2half2_rn(__uint_as_float(lo0) * s,
                                           __uint_as_float(hi0) * s);
            __half2 h1 = __floats2half2_rn(__uint_as_float(lo1) * s,
                                           __uint_as_float(hi1) * s);
            union { uint2 u; __half2 h[2]; } pk;
            pk.h[0] = h0; pk.h[1] = h1;
            *(uint2*)(g_ht1 + (size_t)row * GC + 4 * g) = pk.u;
        }
    }
}

// -------- fused agg(ht1) + layer2 -> ht2 (fp16) ------------------------------
// warp per dst node; lanes: es = lane>>2 (8 edge slots), q = lane&3 (4 ch quads)
__global__ void __launch_bounds__(256) k_agg_l2(const float* __restrict__ W2,
                                                const float* __restrict__ b1,
                                                int n) {
    __shared__ float sW[GC * GC];
    __shared__ float sb[GC];
    if (threadIdx.x < GC * GC) sW[threadIdx.x] = W2[threadIdx.x];
    if (threadIdx.x < GC) sb[threadIdx.x] = b1[threadIdx.x];
    __syncthreads();

    int w = blockIdx.x * 8 + (threadIdx.x >> 5);
    if (w >= n) return;
    int lane = threadIdx.x & 31;
    int q = lane & 3;
    int es = lane >> 2;
    const uint2* htp = (const uint2*)g_ht1;

    float4 a = (es == 0) ? gat4(htp, w, q) : make_float4(0.f, 0.f, 0.f, 0.f);
    int cnt = min(g_cnt[w], CAP);
    const int* bk = g_bucket + (size_t)w * CAP;

    int i = es;
    int s = (i < cnt) ? __ldg(bk + i) : 0;
    while (i < cnt) {
        int nx = (i + 8 < cnt) ? __ldg(bk + i + 8) : 0;
        float4 v = gat4(htp, s, q);
        a.x += v.x; a.y += v.y; a.z += v.z; a.w += v.w;
        i += 8;
        s = nx;
    }
#pragma unroll
    for (int off = 4; off <= 16; off <<= 1) {
        a.x += __shfl_xor_sync(0xffffffffu, a.x, off);
        a.y += __shfl_xor_sync(0xffffffffu, a.y, off);
        a.z += __shfl_xor_sync(0xffffffffu, a.z, off);
        a.w += __shfl_xor_sync(0xffffffffu, a.w, off);
    }
    float sc = g_isq[w];
    float4 z = make_float4(fmaxf(sc * a.x + sb[4 * q + 0], 0.f),
                           fmaxf(sc * a.y + sb[4 * q + 1], 0.f),
                           fmaxf(sc * a.z + sb[4 * q + 2], 0.f),
                           fmaxf(sc * a.w + sb[4 * q + 3], 0.f));
    // 16x16 GEMM: lane computes output channels 4q..4q+3
    float4 o = make_float4(0.f, 0.f, 0.f, 0.f);
#pragma unroll
    for (int kq = 0; kq < 4; kq++) {
        int srcl = (lane & 28) | kq;
        float zk[4];
        zk[0] = __shfl_sync(0xffffffffu, z.x, srcl);
        zk[1] = __shfl_sync(0xffffffffu, z.y, srcl);
        zk[2] = __shfl_sync(0xffffffffu, z.z, srcl);
        zk[3] = __shfl_sync(0xffffffffu, z.w, srcl);
#pragma unroll
        for (int m = 0; m < 4; m++) {
            const float* wr = sW + (4 * kq + m) * GC + 4 * q;
            o.x = fmaf(zk[m], wr[0], o.x);
            o.y = fmaf(zk[m], wr[1], o.y);
            o.z = fmaf(zk[m], wr[2], o.z);
            o.w = fmaf(zk[m], wr[3], o.w);
        }
    }
    if (es == 0) {
        __half2 h0 = __floats2half2_rn(o.x * sc, o.y * sc);
        __half2 h1 = __floats2half2_rn(o.z * sc, o.w * sc);
        union { uint2 u; __half2 h[2]; } pk;
        pk.h[0] = h0; pk.h[1] = h1;
        *(uint2*)(g_ht2 + (size_t)w * GC + 4 * q) = pk.u;
    }
}

// -------- fused agg(ht2) + layer3 -> ht3 (fp32 scalar) -----------------------
__global__ void __launch_bounds__(256) k_agg_l3(const float* __restrict__ W3,
                                                const float* __restrict__ b2,
                                                int n) {
    __shared__ float sW[GC];
    __shared__ float sb[GC];
    if (threadIdx.x < GC) {
        sW[threadIdx.x] = W3[threadIdx.x];
        sb[threadIdx.x] = b2[threadIdx.x];
    }
    __syncthreads();

    int w = blockIdx.x * 8 + (threadIdx.x >> 5);
    if (w >= n) return;
    int lane = threadIdx.x & 31;
    int q = lane & 3;
    int es = lane >> 2;
    const uint2* htp = (const uint2*)g_ht2;

    float4 a = (es == 0) ? gat4(htp, w, q) : make_float4(0.f, 0.f, 0.f, 0.f);
    int cnt = min(g_cnt[w], CAP);
    const int* bk = g_bucket + (size_t)w * CAP;

    int i = es;
    int s = (i < cnt) ? __ldg(bk + i) : 0;
    while (i < cnt) {
        int nx = (i + 8 < cnt) ? __ldg(bk + i + 8) : 0;
        float4 v = gat4(htp, s, q);
        a.x += v.x; a.y += v.y; a.z += v.z; a.w += v.w;
        i += 8;
        s = nx;
    }
#pragma unroll
    for (int off = 4; off <= 16; off <<= 1) {
        a.x += __shfl_xor_sync(0xffffffffu, a.x, off);
        a.y += __shfl_xor_sync(0xffffffffu, a.y, off);
        a.z += __shfl_xor_sync(0xffffffffu, a.z, off);
        a.w += __shfl_xor_sync(0xffffffffu, a.w, off);
    }
    float sc = g_isq[w];
    float p = fmaxf(sc * a.x + sb[4 * q + 0], 0.f) * sW[4 * q + 0]
            + fmaxf(sc * a.y + sb[4 * q + 1], 0.f) * sW[4 * q + 1]
            + fmaxf(sc * a.z + sb[4 * q + 2], 0.f) * sW[4 * q + 2]
            + fmaxf(sc * a.w + sb[4 * q + 3], 0.f) * sW[4 * q + 3];
    p += __shfl_xor_sync(0xffffffffu, p, 1);
    p += __shfl_xor_sync(0xffffffffu, p, 2);
    if (lane == 0) g_ht3[w] = p * sc;
}

// -------- fused agg(ht3) + bias -> out ---------------------------------------
__global__ void __launch_bounds__(256) k_agg_final(const float* __restrict__ b3,
                                                   float* __restrict__ out, int n) {
    int w = blockIdx.x * 8 + (threadIdx.x >> 5);
    if (w >= n) return;
    int lane = threadIdx.x & 31;
    float a = (lane == 0) ? g_ht3[w] : 0.f;
    int cnt = min(g_cnt[w], CAP);
    const int* bk = g_bucket + (size_t)w * CAP;
    for (int i = lane; i < cnt; i += 32) a += __ldg(&g_ht3[__ldg(bk + i)]);
#pragma unroll
    for (int off = 16; off >= 1; off >>= 1)
        a += __shfl_xor_sync(0xffffffffu, a, off);
    if (lane == 0) out[w] = g_isq[w] * a + __ldg(b3);
}

// ---------------- launch -----------------------------------------------------
extern "C" void kernel_launch(void* const* d_in, const int* in_sizes, int n_in,
                              void* d_out, int out_size) {
    const float* x  = (const float*)d_in[0];
    const int*   ei = (const int*)d_in[1];   // int32 edge_index [2, E]
    const float* W1 = (const float*)d_in[2];
    const float* b1 = (const float*)d_in[3];
    const float* W2 = (const float*)d_in[4];
    const float* b2 = (const float*)d_in[5];
    const float* W3 = (const float*)d_in[6];
    const float* b3 = (const float*)d_in[7];
    float* out = (float*)d_out;

    int n = in_sizes[0] / GK;
    int e = in_sizes[1] / 2;
    if (n > GN) n = GN;
    if (e > GE) e = GE;

    int nb = (n + 255) / 256;
    int eb = (e + 255) / 256;
    int wb = (n + 7) / 8;

    k_zero<<<nb, 256>>>(n);
    k_build<<<eb, 256>>>(ei, e, n);
    k_isqrt<<<nb, 256>>>(n);
    k_gemm1<<<(n + 127) / 128, 128>>>(x, W1, n);
    k_agg_l2<<<wb, 256>>>(W2, b1, n);
    k_agg_l3<<<wb, 256>>>(W3, b2, n);
    k_agg_final<<<wb, 256>>>(b3, out, n);
}

// round 10
// speedup vs baseline: 1.0395x; 1.0395x over previous
#include <cuda_runtime.h>
#include <cuda_fp16.h>
#include <cstdint>

// 3-layer GCN, bucket-grouped aggregation, fp16 message payloads.
//   ht = (hW)*isq per node (fp16);  acc[d] = ht[d] + sum_{s->d} ht[s] (fp32);
//   next layer input = relu(isq*acc + b). One edge pass builds per-dst buckets.
// GEMM1: k-pair-packed FFMA2, x tile in smem (broadcast reads), W^T k-pairs in
// smem; thread = 1 channel x 8 rows -> 16 acc regs, fma-pipe-bound.
// edge_index arrives as int32 (JAX x64-disabled demotes int64).

#define GN 100000
#define GE 3200000
#define GK 512
#define GC 16
#define CAP 128      // bucket slots per node; P(deg>128) ~ 1e-60

#define ROWS_B 128   // rows per gemm block
#define KCH 64       // k per staged chunk
#define XS_PITCH 68  // floats per xs row (64 + 4 pad)
#define WT_PITCH 258 // u64 (k-pairs) per wt channel row (256 + 2 pad)
#define XS_BYTES (ROWS_B * XS_PITCH * 4)          // 34816
#define SMEM_TOTAL (XS_BYTES + GC * WT_PITCH * 8) // 34816 + 33024 = 67840

// ---------------- scratch (static device globals) ----------------------------
__device__ __align__(256) float  g_isq[GN];
__device__ __align__(256) __half g_ht1[GN * GC];
__device__ __align__(256) __half g_ht2[GN * GC];
__device__ __align__(256) float  g_ht3[GN];
__device__ __align__(256) int    g_cnt[GN];
__device__ __align__(256) int    g_bucket[(size_t)GN * CAP];  // 51.2 MB

// ---------------- helpers -----------------------------------------------------
__device__ __forceinline__ unsigned long long ffma2(unsigned long long a,
                                                    unsigned long long b,
                                                    unsigned long long c) {
    unsigned long long d;
    asm("fma.rn.f32x2 %0, %1, %2, %3;" : "=l"(d) : "l"(a), "l"(b), "l"(c));
    return d;
}

__device__ __forceinline__ float4 gat4(const uint2* __restrict__ htp, int s, int q) {
    uint2 u = __ldg(htp + (size_t)s * 4 + q);
    __half2 h0 = *(__half2*)&u.x;
    __half2 h1 = *(__half2*)&u.y;
    float2 a = __half22float2(h0), b = __half22float2(h1);
    return make_float4(a.x, a.y, b.x, b.y);
}

// ---------------- prep -------------------------------------------------------
__global__ void k_zero(int n) {
    int i = blockIdx.x * blockDim.x + threadIdx.x;
    if (i < n) g_cnt[i] = 0;
}

__global__ void k_build(const int* __restrict__ ei, int e, int n) {
    int i = blockIdx.x * blockDim.x + threadIdx.x;
    if (i >= e) return;
    int s = ei[i];
    int d = ei[e + i];
    if ((unsigned)s >= (unsigned)n || (unsigned)d >= (unsigned)n) return;
    int pos = atomicAdd(&g_cnt[d], 1);
    if (pos < CAP) g_bucket[(size_t)d * CAP + pos] = s;
}

__global__ void k_isqrt(int n) {
    int i = blockIdx.x * blockDim.x + threadIdx.x;
    if (i < n) g_isq[i] = rsqrtf((float)g_cnt[i] + 1.0f);
}

// ---------------- GEMM1: ht1 = fp16((x @ W1) * isq) --------------------------
// 256 thr, 128 rows/block. c = t&15 (channel), slot = t>>4 (row slot 0..15);
// thread accumulates rows slot+16j (j=0..7) for channel c as k-pair f32x2.
__global__ void __launch_bounds__(256, 3) k_gemm1(const float* __restrict__ x,
                                                  const float* __restrict__ W1,
                                                  int n) {
    extern __shared__ __align__(16) char dsm[];
    float* xs = (float*)dsm;
    unsigned long long* wt = (unsigned long long*)(dsm + XS_BYTES);

    int t = threadIdx.x;
    int c = t & 15;
    int slot = t >> 4;

    // stage W^T as k-pairs: wt[c][kp] = (W1[2kp][c], W1[2kp+1][c])
#pragma unroll
    for (int i = 0; i < 16; i++) {
        int idx = t + 256 * i;       // 0..4095
        int cc = idx >> 8, kp = idx & 255;
        union { float2 f; unsigned long long u; } pk;
        pk.f.x = W1[(size_t)(2 * kp) * GC + cc];
        pk.f.y = W1[(size_t)(2 * kp + 1) * GC + cc];
        wt[cc * WT_PITCH + kp] = pk.u;
    }

    unsigned long long acc[8];
#pragma unroll
    for (int j = 0; j < 8; j++) acc[j] = 0ull;

    const float4* x4 = (const float4*)x;
    const float* xs_th = xs + slot * XS_PITCH;

    for (int kb = 0; kb < GK; kb += KCH) {
        __syncthreads();
        // stage x tile: 128 rows x 64 k, coalesced float4
#pragma unroll
        for (int i = 0; i < 8; i++) {
            int idx = t + 256 * i;   // 0..2047
            int r = idx >> 4, f4 = idx & 15;
            int gr = blockIdx.x * ROWS_B + r;
            if (gr >= n) gr = n - 1;
            float4 v = __ldg(x4 + (size_t)gr * (GK / 4) + (kb >> 2) + f4);
            *(float4*)(xs + r * XS_PITCH + 4 * f4) = v;
        }
        __syncthreads();

        const unsigned long long* wc = wt + c * WT_PITCH + (kb >> 1);
#pragma unroll 4
        for (int k4 = 0; k4 < KCH / 4; k4++) {
            ulonglong2 wv = *(const ulonglong2*)(wc + 2 * k4);
#pragma unroll
            for (int j = 0; j < 8; j++) {
                ulonglong2 xv =
                    *(const ulonglong2*)(xs_th + j * 16 * XS_PITCH + 4 * k4);
                acc[j] = ffma2(xv.x, wv.x, acc[j]);
                acc[j] = ffma2(xv.y, wv.y, acc[j]);
            }
        }
    }

    // epilogue: sum k-pair partials, scale by isq, store fp16
#pragma unroll
    for (int j = 0; j < 8; j++) {
        int row = blockIdx.x * ROWS_B + slot + 16 * j;
        if (row < n) {
            unsigned lo, hi;
            asm("mov.b64 {%0,%1}, %2;" : "=r"(lo), "=r"(hi) : "l"(acc[j]));
            float v = (__uint_as_float(lo) + __uint_as_float(hi)) * g_isq[row];
            g_ht1[(size_t)row * GC + c] = __float2half(v);
        }
    }
}

// -------- fused agg(ht1) + layer2 -> ht2 (fp16) ------------------------------
__global__ void __launch_bounds__(256) k_agg_l2(const float* __restrict__ W2,
                                                const float* __restrict__ b1,
                                                int n) {
    __shared__ float sW[GC * GC];
    __shared__ float sb[GC];
    if (threadIdx.x < GC * GC) sW[threadIdx.x] = W2[threadIdx.x];
    if (threadIdx.x < GC) sb[threadIdx.x] = b1[threadIdx.x];
    __syncthreads();

    int w = blockIdx.x * 8 + (threadIdx.x >> 5);
    if (w >= n) return;
    int lane = threadIdx.x & 31;
    int q = lane & 3;
    int es = lane >> 2;
    const uint2* htp = (const uint2*)g_ht1;

    float4 a = (es == 0) ? gat4(htp, w, q) : make_float4(0.f, 0.f, 0.f, 0.f);
    int cnt = min(g_cnt[w], CAP);
    const int* bk = g_bucket + (size_t)w * CAP;

    int i = es;
    int s = (i < cnt) ? __ldg(bk + i) : 0;
    while (i < cnt) {
        int nx = (i + 8 < cnt) ? __ldg(bk + i + 8) : 0;
        float4 v = gat4(htp, s, q);
        a.x += v.x; a.y += v.y; a.z += v.z; a.w += v.w;
        i += 8;
        s = nx;
    }
#pragma unroll
    for (int off = 4; off <= 16; off <<= 1) {
        a.x += __shfl_xor_sync(0xffffffffu, a.x, off);
        a.y += __shfl_xor_sync(0xffffffffu, a.y, off);
        a.z += __shfl_xor_sync(0xffffffffu, a.z, off);
        a.w += __shfl_xor_sync(0xffffffffu, a.w, off);
    }
    float sc = g_isq[w];
    float4 z = make_float4(fmaxf(sc * a.x + sb[4 * q + 0], 0.f),
                           fmaxf(sc * a.y + sb[4 * q + 1], 0.f),
                           fmaxf(sc * a.z + sb[4 * q + 2], 0.f),
                           fmaxf(sc * a.w + sb[4 * q + 3], 0.f));
    float4 o = make_float4(0.f, 0.f, 0.f, 0.f);
#pragma unroll
    for (int kq = 0; kq < 4; kq++) {
        int srcl = (lane & 28) | kq;
        float zk[4];
        zk[0] = __shfl_sync(0xffffffffu, z.x, srcl);
        zk[1] = __shfl_sync(0xffffffffu, z.y, srcl);
        zk[2] = __shfl_sync(0xffffffffu, z.z, srcl);
        zk[3] = __shfl_sync(0xffffffffu, z.w, srcl);
#pragma unroll
        for (int m = 0; m < 4; m++) {
            const float* wr = sW + (4 * kq + m) * GC + 4 * q;
            o.x = fmaf(zk[m], wr[0], o.x);
            o.y = fmaf(zk[m], wr[1], o.y);
            o.z = fmaf(zk[m], wr[2], o.z);
            o.w = fmaf(zk[m], wr[3], o.w);
        }
    }
    if (es == 0) {
        __half2 h0 = __floats2half2_rn(o.x * sc, o.y * sc);
        __half2 h1 = __floats2half2_rn(o.z * sc, o.w * sc);
        union { uint2 u; __half2 h[2]; } pk;
        pk.h[0] = h0; pk.h[1] = h1;
        *(uint2*)(g_ht2 + (size_t)w * GC + 4 * q) = pk.u;
    }
}

// -------- fused agg(ht2) + layer3 -> ht3 (fp32 scalar) -----------------------
__global__ void __launch_bounds__(256) k_agg_l3(const float* __restrict__ W3,
                                                const float* __restrict__ b2,
                                                int n) {
    __shared__ float sW[GC];
    __shared__ float sb[GC];
    if (threadIdx.x < GC) {
        sW[threadIdx.x] = W3[threadIdx.x];
        sb[threadIdx.x] = b2[threadIdx.x];
    }
    __syncthreads();

    int w = blockIdx.x * 8 + (threadIdx.x >> 5);
    if (w >= n) return;
    int lane = threadIdx.x & 31;
    int q = lane & 3;
    int es = lane >> 2;
    const uint2* htp = (const uint2*)g_ht2;

    float4 a = (es == 0) ? gat4(htp, w, q) : make_float4(0.f, 0.f, 0.f, 0.f);
    int cnt = min(g_cnt[w], CAP);
    const int* bk = g_bucket + (size_t)w * CAP;

    int i = es;
    int s = (i < cnt) ? __ldg(bk + i) : 0;
    while (i < cnt) {
        int nx = (i + 8 < cnt) ? __ldg(bk + i + 8) : 0;
        float4 v = gat4(htp, s, q);
        a.x += v.x; a.y += v.y; a.z += v.z; a.w += v.w;
        i += 8;
        s = nx;
    }
#pragma unroll
    for (int off = 4; off <= 16; off <<= 1) {
        a.x += __shfl_xor_sync(0xffffffffu, a.x, off);
        a.y += __shfl_xor_sync(0xffffffffu, a.y, off);
        a.z += __shfl_xor_sync(0xffffffffu, a.z, off);
        a.w += __shfl_xor_sync(0xffffffffu, a.w, off);
    }
    float sc = g_isq[w];
    float p = fmaxf(sc * a.x + sb[4 * q + 0], 0.f) * sW[4 * q + 0]
            + fmaxf(sc * a.y + sb[4 * q + 1], 0.f) * sW[4 * q + 1]
            + fmaxf(sc * a.z + sb[4 * q + 2], 0.f) * sW[4 * q + 2]
            + fmaxf(sc * a.w + sb[4 * q + 3], 0.f) * sW[4 * q + 3];
    p += __shfl_xor_sync(0xffffffffu, p, 1);
    p += __shfl_xor_sync(0xffffffffu, p, 2);
    if (lane == 0) g_ht3[w] = p * sc;
}

// -------- fused agg(ht3) + bias -> out ---------------------------------------
__global__ void __launch_bounds__(256) k_agg_final(const float* __restrict__ b3,
                                                   float* __restrict__ out, int n) {
    int w = blockIdx.x * 8 + (threadIdx.x >> 5);
    if (w >= n) return;
    int lane = threadIdx.x & 31;
    float a = (lane == 0) ? g_ht3[w] : 0.f;
    int cnt = min(g_cnt[w], CAP);
    const int* bk = g_bucket + (size_t)w * CAP;
    for (int i = lane; i < cnt; i += 32) a += __ldg(&g_ht3[__ldg(bk + i)]);
#pragma unroll
    for (int off = 16; off >= 1; off >>= 1)
        a += __shfl_xor_sync(0xffffffffu, a, off);
    if (lane == 0) out[w] = g_isq[w] * a + __ldg(b3);
}

// ---------------- launch -----------------------------------------------------
extern "C" void kernel_launch(void* const* d_in, const int* in_sizes, int n_in,
                              void* d_out, int out_size) {
    const float* x  = (const float*)d_in[0];
    const int*   ei = (const int*)d_in[1];   // int32 edge_index [2, E]
    const float* W1 = (const float*)d_in[2];
    const float* b1 = (const float*)d_in[3];
    const float* W2 = (const float*)d_in[4];
    const float* b2 = (const float*)d_in[5];
    const float* W3 = (const float*)d_in[6];
    const float* b3 = (const float*)d_in[7];
    float* out = (float*)d_out;

    int n = in_sizes[0] / GK;
    int e = in_sizes[1] / 2;
    if (n > GN) n = GN;
    if (e > GE) e = GE;

    int nb = (n + 255) / 256;
    int eb = (e + 255) / 256;
    int wb = (n + 7) / 8;

    static int smem_set = 0;
    if (!smem_set) {
        cudaFuncSetAttribute(k_gemm1, cudaFuncAttributeMaxDynamicSharedMemorySize,
                             SMEM_TOTAL);
        smem_set = 1;
    }

    k_zero<<<nb, 256>>>(n);
    k_build<<<eb, 256>>>(ei, e, n);
    k_isqrt<<<nb, 256>>>(n);
    k_gemm1<<<(n + ROWS_B - 1) / ROWS_B, 256, SMEM_TOTAL>>>(x, W1, n);
    k_agg_l2<<<wb, 256>>>(W2, b1, n);
    k_agg_l3<<<wb, 256>>>(W3, b2, n);
    k_agg_final<<<wb, 256>>>(b3, out, n);
}

// round 11
// speedup vs baseline: 1.1113x; 1.0691x over previous
#include <cuda_runtime.h>
#include <cuda_fp16.h>
#include <cstdint>

// 3-layer GCN, bucket-grouped aggregation, fp16 message payloads.
//   ht = (hW)*isq per node (fp16);  acc[d] = ht[d] + sum_{s->d} ht[s] (fp32);
//   next layer input = relu(isq*acc + b). One edge pass builds per-dst buckets.
// GEMM1: cp.async double-buffered x tiles + k-pair FFMA2; thread = 1 ch x 8 rows.
// edge_index arrives as int32 (JAX x64-disabled demotes int64).

#define GN 100000
#define GE 3200000
#define GK 512
#define GC 16
#define CAP 128      // bucket slots per node; P(deg>128) ~ 1e-60

#define ROWS_B 128   // rows per gemm block
#define KCH 32       // k per staged chunk
#define NCHUNK (GK / KCH)
#define XS_PITCH 36  // floats per xs row (32 + 4 pad)
#define WT_PITCH 258 // u64 (k-pairs) per wt channel row (256 + 2 pad)
#define XS_BUF (ROWS_B * XS_PITCH * 4)                 // 18432 B per buffer
#define SMEM_TOTAL (2 * XS_BUF + GC * WT_PITCH * 8)    // 36864 + 33024 = 69888

// ---------------- scratch (static device globals) ----------------------------
__device__ __align__(256) float  g_isq[GN];
__device__ __align__(256) __half g_ht1[GN * GC];
__device__ __align__(256) __half g_ht2[GN * GC];
__device__ __align__(256) float  g_ht3[GN];
__device__ __align__(256) int    g_cnt[GN];
__device__ __align__(256) int    g_bucket[(size_t)GN * CAP];  // 51.2 MB

// ---------------- helpers -----------------------------------------------------
__device__ __forceinline__ unsigned long long ffma2(unsigned long long a,
                                                    unsigned long long b,
                                                    unsigned long long c) {
    unsigned long long d;
    asm("fma.rn.f32x2 %0, %1, %2, %3;" : "=l"(d) : "l"(a), "l"(b), "l"(c));
    return d;
}

__device__ __forceinline__ void cp_async16(uint32_t dst, const void* src) {
    asm volatile("cp.async.cg.shared.global [%0], [%1], 16;"
                 :: "r"(dst), "l"(src) : "memory");
}

__device__ __forceinline__ float4 gat4(const uint2* __restrict__ htp, int s, int q) {
    uint2 u = __ldg(htp + (size_t)s * 4 + q);
    __half2 h0 = *(__half2*)&u.x;
    __half2 h1 = *(__half2*)&u.y;
    float2 a = __half22float2(h0), b = __half22float2(h1);
    return make_float4(a.x, a.y, b.x, b.y);
}

// ---------------- prep -------------------------------------------------------
__global__ void k_zero(int n) {
    int i = blockIdx.x * blockDim.x + threadIdx.x;
    if (i < n) g_cnt[i] = 0;
}

__global__ void k_build(const int* __restrict__ ei, int e, int n) {
    int i = blockIdx.x * blockDim.x + threadIdx.x;
    if (i >= e) return;
    int s = ei[i];
    int d = ei[e + i];
    if ((unsigned)s >= (unsigned)n || (unsigned)d >= (unsigned)n) return;
    int pos = atomicAdd(&g_cnt[d], 1);
    if (pos < CAP) g_bucket[(size_t)d * CAP + pos] = s;
}

__global__ void k_isqrt(int n) {
    int i = blockIdx.x * blockDim.x + threadIdx.x;
    if (i < n) g_isq[i] = rsqrtf((float)g_cnt[i] + 1.0f);
}

// ---------------- GEMM1: ht1 = fp16((x @ W1) * isq) --------------------------
// 256 thr, 128 rows/block. c = t&15 (channel), slot = t>>4 (row slot 0..15);
// thread accumulates rows slot+16j (j=0..7) for channel c as k-pair f32x2.
// x tiles double-buffered via cp.async.cg; compute overlaps next-tile loads.
__global__ void __launch_bounds__(256) k_gemm1(const float* __restrict__ x,
                                               const float* __restrict__ W1,
                                               int n) {
    extern __shared__ __align__(16) char dsm[];
    float* xs = (float*)dsm;                              // [2][128][36]
    unsigned long long* wt = (unsigned long long*)(dsm + 2 * XS_BUF);
    uint32_t xs_sa = (uint32_t)__cvta_generic_to_shared(dsm);

    int t = threadIdx.x;
    int c = t & 15;
    int slot = t >> 4;
    const float4* x4 = (const float4*)x;

    // stage W^T as k-pairs: wt[c][kp] = (W1[2kp][c], W1[2kp+1][c])
#pragma unroll
    for (int i = 0; i < 16; i++) {
        int idx = t + 256 * i;       // 0..4095
        int cc = idx >> 8, kp = idx & 255;
        union { float2 f; unsigned long long u; } pk;
        pk.f.x = W1[(size_t)(2 * kp) * GC + cc];
        pk.f.y = W1[(size_t)(2 * kp + 1) * GC + cc];
        wt[cc * WT_PITCH + kp] = pk.u;
    }

    // stage chunk into buffer via cp.async: 1024 float4s, 4 per thread
    auto stage = [&](int chunk, int buf) {
#pragma unroll
        for (int i = 0; i < 4; i++) {
            int idx = t + 256 * i;   // 0..1023
            int r = idx >> 3, f4 = idx & 7;
            int gr = blockIdx.x * ROWS_B + r;
            if (gr >= n) gr = n - 1;
            const float4* src = x4 + (size_t)gr * (GK / 4) + chunk * (KCH / 4) + f4;
            uint32_t dst = xs_sa + (uint32_t)(buf * XS_BUF +
                                              (r * XS_PITCH + 4 * f4) * 4);
            cp_async16(dst, src);
        }
        asm volatile("cp.async.commit_group;" ::: "memory");
    };

    unsigned long long acc[8];
#pragma unroll
    for (int j = 0; j < 8; j++) acc[j] = 0ull;

    stage(0, 0);
    for (int ch = 0; ch < NCHUNK; ch++) {
        if (ch + 1 < NCHUNK) {
            stage(ch + 1, (ch + 1) & 1);
            asm volatile("cp.async.wait_group 1;" ::: "memory");
        } else {
            asm volatile("cp.async.wait_group 0;" ::: "memory");
        }
        __syncthreads();

        const float* xs_th = xs + (ch & 1) * (ROWS_B * XS_PITCH) + slot * XS_PITCH;
        const unsigned long long* wc = wt + c * WT_PITCH + ch * (KCH / 2);
#pragma unroll
        for (int k4 = 0; k4 < KCH / 4; k4++) {
            ulonglong2 wv = *(const ulonglong2*)(wc + 2 * k4);
#pragma unroll
            for (int j = 0; j < 8; j++) {
                ulonglong2 xv =
                    *(const ulonglong2*)(xs_th + j * 16 * XS_PITCH + 4 * k4);
                acc[j] = ffma2(xv.x, wv.x, acc[j]);
                acc[j] = ffma2(xv.y, wv.y, acc[j]);
            }
        }
        __syncthreads();   // protect buffer (ch+1)&1 staged next iteration
    }

    // epilogue: sum k-pair partials, scale by isq, store fp16
#pragma unroll
    for (int j = 0; j < 8; j++) {
        int row = blockIdx.x * ROWS_B + slot + 16 * j;
        if (row < n) {
            unsigned lo, hi;
            asm("mov.b64 {%0,%1}, %2;" : "=r"(lo), "=r"(hi) : "l"(acc[j]));
            float v = (__uint_as_float(lo) + __uint_as_float(hi)) * g_isq[row];
            g_ht1[(size_t)row * GC + c] = __float2half(v);
        }
    }
}

// -------- fused agg(ht1) + layer2 -> ht2 (fp16) ------------------------------
__global__ void __launch_bounds__(256) k_agg_l2(const float* __restrict__ W2,
                                                const float* __restrict__ b1,
                                                int n) {
    __shared__ float sW[GC * GC];
    __shared__ float sb[GC];
    if (threadIdx.x < GC * GC) sW[threadIdx.x] = W2[threadIdx.x];
    if (threadIdx.x < GC) sb[threadIdx.x] = b1[threadIdx.x];
    __syncthreads();

    int w = blockIdx.x * 8 + (threadIdx.x >> 5);
    if (w >= n) return;
    int lane = threadIdx.x & 31;
    int q = lane & 3;
    int es = lane >> 2;
    const uint2* htp = (const uint2*)g_ht1;

    float4 a = (es == 0) ? gat4(htp, w, q) : make_float4(0.f, 0.f, 0.f, 0.f);
    int cnt = min(g_cnt[w], CAP);
    const int* bk = g_bucket + (size_t)w * CAP;

    int i = es;
    int s = (i < cnt) ? __ldg(bk + i) : 0;
    while (i < cnt) {
        int nx = (i + 8 < cnt) ? __ldg(bk + i + 8) : 0;
        float4 v = gat4(htp, s, q);
        a.x += v.x; a.y += v.y; a.z += v.z; a.w += v.w;
        i += 8;
        s = nx;
    }
#pragma unroll
    for (int off = 4; off <= 16; off <<= 1) {
        a.x += __shfl_xor_sync(0xffffffffu, a.x, off);
        a.y += __shfl_xor_sync(0xffffffffu, a.y, off);
        a.z += __shfl_xor_sync(0xffffffffu, a.z, off);
        a.w += __shfl_xor_sync(0xffffffffu, a.w, off);
    }
    float sc = g_isq[w];
    float4 z = make_float4(fmaxf(sc * a.x + sb[4 * q + 0], 0.f),
                           fmaxf(sc * a.y + sb[4 * q + 1], 0.f),
                           fmaxf(sc * a.z + sb[4 * q + 2], 0.f),
                           fmaxf(sc * a.w + sb[4 * q + 3], 0.f));
    float4 o = make_float4(0.f, 0.f, 0.f, 0.f);
#pragma unroll
    for (int kq = 0; kq < 4; kq++) {
        int srcl = (lane & 28) | kq;
        float zk[4];
        zk[0] = __shfl_sync(0xffffffffu, z.x, srcl);
        zk[1] = __shfl_sync(0xffffffffu, z.y, srcl);
        zk[2] = __shfl_sync(0xffffffffu, z.z, srcl);
        zk[3] = __shfl_sync(0xffffffffu, z.w, srcl);
#pragma unroll
        for (int m = 0; m < 4; m++) {
            const float* wr = sW + (4 * kq + m) * GC + 4 * q;
            o.x = fmaf(zk[m], wr[0], o.x);
            o.y = fmaf(zk[m], wr[1], o.y);
            o.z = fmaf(zk[m], wr[2], o.z);
            o.w = fmaf(zk[m], wr[3], o.w);
        }
    }
    if (es == 0) {
        __half2 h0 = __floats2half2_rn(o.x * sc, o.y * sc);
        __half2 h1 = __floats2half2_rn(o.z * sc, o.w * sc);
        union { uint2 u; __half2 h[2]; } pk;
        pk.h[0] = h0; pk.h[1] = h1;
        *(uint2*)(g_ht2 + (size_t)w * GC + 4 * q) = pk.u;
    }
}

// -------- fused agg(ht2) + layer3 -> ht3 (fp32 scalar) -----------------------
__global__ void __launch_bounds__(256) k_agg_l3(const float* __restrict__ W3,
                                                const float* __restrict__ b2,
                                                int n) {
    __shared__ float sW[GC];
    __shared__ float sb[GC];
    if (threadIdx.x < GC) {
        sW[threadIdx.x] = W3[threadIdx.x];
        sb[threadIdx.x] = b2[threadIdx.x];
    }
    __syncthreads();

    int w = blockIdx.x * 8 + (threadIdx.x >> 5);
    if (w >= n) return;
    int lane = threadIdx.x & 31;
    int q = lane & 3;
    int es = lane >> 2;
    const uint2* htp = (const uint2*)g_ht2;

    float4 a = (es == 0) ? gat4(htp, w, q) : make_float4(0.f, 0.f, 0.f, 0.f);
    int cnt = min(g_cnt[w], CAP);
    const int* bk = g_bucket + (size_t)w * CAP;

    int i = es;
    int s = (i < cnt) ? __ldg(bk + i) : 0;
    while (i < cnt) {
        int nx = (i + 8 < cnt) ? __ldg(bk + i + 8) : 0;
        float4 v = gat4(htp, s, q);
        a.x += v.x; a.y += v.y; a.z += v.z; a.w += v.w;
        i += 8;
        s = nx;
    }
#pragma unroll
    for (int off = 4; off <= 16; off <<= 1) {
        a.x += __shfl_xor_sync(0xffffffffu, a.x, off);
        a.y += __shfl_xor_sync(0xffffffffu, a.y, off);
        a.z += __shfl_xor_sync(0xffffffffu, a.z, off);
        a.w += __shfl_xor_sync(0xffffffffu, a.w, off);
    }
    float sc = g_isq[w];
    float p = fmaxf(sc * a.x + sb[4 * q + 0], 0.f) * sW[4 * q + 0]
            + fmaxf(sc * a.y + sb[4 * q + 1], 0.f) * sW[4 * q + 1]
            + fmaxf(sc * a.z + sb[4 * q + 2], 0.f) * sW[4 * q + 2]
            + fmaxf(sc * a.w + sb[4 * q + 3], 0.f) * sW[4 * q + 3];
    p += __shfl_xor_sync(0xffffffffu, p, 1);
    p += __shfl_xor_sync(0xffffffffu, p, 2);
    if (lane == 0) g_ht3[w] = p * sc;
}

// -------- fused agg(ht3) + bias -> out ---------------------------------------
__global__ void __launch_bounds__(256) k_agg_final(const float* __restrict__ b3,
                                                   float* __restrict__ out, int n) {
    int w = blockIdx.x * 8 + (threadIdx.x >> 5);
    if (w >= n) return;
    int lane = threadIdx.x & 31;
    float a = (lane == 0) ? g_ht3[w] : 0.f;
    int cnt = min(g_cnt[w], CAP);
    const int* bk = g_bucket + (size_t)w * CAP;
    for (int i = lane; i < cnt; i += 32) a += __ldg(&g_ht3[__ldg(bk + i)]);
#pragma unroll
    for (int off = 16; off >= 1; off >>= 1)
        a += __shfl_xor_sync(0xffffffffu, a, off);
    if (lane == 0) out[w] = g_isq[w] * a + __ldg(b3);
}

// ---------------- launch -----------------------------------------------------
extern "C" void kernel_launch(void* const* d_in, const int* in_sizes, int n_in,
                              void* d_out, int out_size) {
    const float* x  = (const float*)d_in[0];
    const int*   ei = (const int*)d_in[1];   // int32 edge_index [2, E]
    const float* W1 = (const float*)d_in[2];
    const float* b1 = (const float*)d_in[3];
    const float* W2 = (const float*)d_in[4];
    const float* b2 = (const float*)d_in[5];
    const float* W3 = (const float*)d_in[6];
    const float* b3 = (const float*)d_in[7];
    float* out = (float*)d_out;

    int n = in_sizes[0] / GK;
    int e = in_sizes[1] / 2;
    if (n > GN) n = GN;
    if (e > GE) e = GE;

    int nb = (n + 255) / 256;
    int eb = (e + 255) / 256;
    int wb = (n + 7) / 8;

    static int smem_set = 0;
    if (!smem_set) {
        cudaFuncSetAttribute(k_gemm1, cudaFuncAttributeMaxDynamicSharedMemorySize,
                             SMEM_TOTAL);
        smem_set = 1;
    }

    k_zero<<<nb, 256>>>(n);
    k_build<<<eb, 256>>>(ei, e, n);
    k_isqrt<<<nb, 256>>>(n);
    k_gemm1<<<(n + ROWS_B - 1) / ROWS_B, 256, SMEM_TOTAL>>>(x, W1, n);
    k_agg_l2<<<wb, 256>>>(W2, b1, n);
    k_agg_l3<<<wb, 256>>>(W3, b2, n);
    k_agg_final<<<wb, 256>>>(b3, out, n);
}